// round 4
// baseline (speedup 1.0000x reference)
#include <cuda_runtime.h>
#include <math_constants.h>

// Analytic collapse of the 18-qubit circuit (derivation in R1):
//   theta_{b,i} = (x_{b,i} - min(x)) / (max(x) - min(x)) * 2*pi - pi
//   <Z_i>_b = cos(a_i)cos(b_i)*cos(th_i) - sin(b_i)*sin(th_i)*cos(th_{i-1})*cos(th_{i+1})
//   out_b = sum_i head_w[i] * <Z_i>_b + head_b
// R4: single-warp CTAs (32 threads, 9 float4 loads/lane) — no smem, no
// __syncthreads, fully warp-synchronous. One CTA per batch row.

#define NW 18
#define NB 64
#define NELEM (NB * NW)   // 1152
#define NVEC  (NELEM / 4) // 288 = 32 * 9

__global__ void __launch_bounds__(32, 1)
qcircuit_analytic_kernel(const float* __restrict__ sb,
                         const float* __restrict__ params,
                         const float* __restrict__ hw,
                         const float* __restrict__ hb,
                         float* __restrict__ out) {
    const int lane = threadIdx.x;
    const int row  = blockIdx.x;

    // ---- full min/max over all 1152 inputs: 9 float4 per lane (MLP=9) ----
    const float4* sb4 = (const float4*)sb;
    float4 v0 = sb4[lane];
    float4 v1 = sb4[lane + 32];
    float4 v2 = sb4[lane + 64];
    float4 v3 = sb4[lane + 96];
    float4 v4 = sb4[lane + 128];
    float4 v5 = sb4[lane + 160];
    float4 v6 = sb4[lane + 192];
    float4 v7 = sb4[lane + 224];
    float4 v8 = sb4[lane + 256];

    // ---- per-wire constants on lanes < NW (overlaps load latency) ----
    float cA = 0.0f, sB = 0.0f, wgt = 0.0f, bias = 0.0f;
    if (lane < NW) {
        float alpha = params[lane * 3 + 0];
        float beta  = params[lane * 3 + 1];
        cA  = __cosf(alpha) * __cosf(beta);
        sB  = __sinf(beta);
        wgt = hw[lane];
    }
    if (lane == 0) bias = hb[0];

    float mn, mx;
    {
        float a0 = fminf(fminf(v0.x, v0.y), fminf(v0.z, v0.w));
        float a1 = fminf(fminf(v1.x, v1.y), fminf(v1.z, v1.w));
        float a2 = fminf(fminf(v2.x, v2.y), fminf(v2.z, v2.w));
        float a3 = fminf(fminf(v3.x, v3.y), fminf(v3.z, v3.w));
        float a4 = fminf(fminf(v4.x, v4.y), fminf(v4.z, v4.w));
        float a5 = fminf(fminf(v5.x, v5.y), fminf(v5.z, v5.w));
        float a6 = fminf(fminf(v6.x, v6.y), fminf(v6.z, v6.w));
        float a7 = fminf(fminf(v7.x, v7.y), fminf(v7.z, v7.w));
        float a8 = fminf(fminf(v8.x, v8.y), fminf(v8.z, v8.w));
        mn = fminf(fminf(fminf(a0, a1), fminf(a2, a3)),
                   fminf(fminf(a4, a5), fminf(a6, fminf(a7, a8))));
        float b0 = fmaxf(fmaxf(v0.x, v0.y), fmaxf(v0.z, v0.w));
        float b1 = fmaxf(fmaxf(v1.x, v1.y), fmaxf(v1.z, v1.w));
        float b2 = fmaxf(fmaxf(v2.x, v2.y), fmaxf(v2.z, v2.w));
        float b3 = fmaxf(fmaxf(v3.x, v3.y), fmaxf(v3.z, v3.w));
        float b4 = fmaxf(fmaxf(v4.x, v4.y), fmaxf(v4.z, v4.w));
        float b5 = fmaxf(fmaxf(v5.x, v5.y), fmaxf(v5.z, v5.w));
        float b6 = fmaxf(fmaxf(v6.x, v6.y), fmaxf(v6.z, v6.w));
        float b7 = fmaxf(fmaxf(v7.x, v7.y), fmaxf(v7.z, v7.w));
        float b8 = fmaxf(fmaxf(v8.x, v8.y), fmaxf(v8.z, v8.w));
        mx = fmaxf(fmaxf(fmaxf(b0, b1), fmaxf(b2, b3)),
                   fmaxf(fmaxf(b4, b5), fmaxf(b6, fmaxf(b7, b8))));
    }

    // ---- warp min/max reduce (two independent shfl chains, pipelined) ----
#pragma unroll
    for (int s = 16; s > 0; s >>= 1) {
        mn = fminf(mn, __shfl_xor_sync(0xFFFFFFFFu, mn, s));
        mx = fmaxf(mx, __shfl_xor_sync(0xFFFFFFFFu, mx, s));
    }

    const float scale = (2.0f * CUDART_PI_F) / (mx - mn);

    // ---- lanes 0..17: one wire each for this block's row ----
    int idx = row * NW + lane;
    if (idx > NELEM - 1) idx = NELEM - 1;        // lanes >= NW: in-bounds dummy
    float theta = (sb[idx] - mn) * scale - CUDART_PI_F;  // L1 hit (warm from above)
    float sz, cz;
    __sincosf(theta, &sz, &cz);

    float zl = __shfl_up_sync(0xFFFFFFFFu, cz, 1);    // cz[i-1]
    float zr = __shfl_down_sync(0xFFFFFFFFu, cz, 1);  // cz[i+1]
    if (lane == 0)      zl = 1.0f;
    if (lane == NW - 1) zr = 1.0f;

    float term = wgt * fmaf(cA, cz, -sB * sz * zl * zr) + bias;  // wgt=0 on lanes>=NW

#pragma unroll
    for (int s = 16; s > 0; s >>= 1)
        term += __shfl_xor_sync(0xFFFFFFFFu, term, s);

    if (lane == 0) out[row] = term;
}

extern "C" void kernel_launch(void* const* d_in, const int* in_sizes, int n_in,
                              void* d_out, int out_size) {
    const float* state_batch = (const float*)d_in[0]; // (64, 18)
    const float* params      = (const float*)d_in[1]; // (18, 3)
    const float* head_w      = (const float*)d_in[2]; // (1, 18)
    const float* head_b      = (const float*)d_in[3]; // (1,)
    float* out = (float*)d_out;                       // (64,)

    qcircuit_analytic_kernel<<<NB, 32>>>(state_batch, params, head_w, head_b, out);
}

// round 6
// speedup vs baseline: 1.0048x; 1.0048x over previous
#include <cuda_runtime.h>
#include <math_constants.h>

// Analytic collapse of the 18-qubit circuit (derivation in R1):
//   theta_{b,i} = (x_{b,i} - min(x)) / (max(x) - min(x)) * 2*pi - pi
//   <Z_i>_b = cos(a_i)cos(b_i)*cos(th_i) - sin(b_i)*sin(th_i)*cos(th_{i-1})*cos(th_{i+1})
//   out_b = sum_i head_w[i] * <Z_i>_b + head_b
// R6: R4 structure (redux.f32 does not exist on sm_103a) + __fdividef (MUFU
// RCP) for the scale, hoisted row load, fused -pi. Single-warp CTA per row.

#define NW 18
#define NB 64
#define NELEM (NB * NW)   // 1152
#define NVEC  (NELEM / 4) // 288 = 32 * 9

__global__ void __launch_bounds__(32, 1)
qcircuit_analytic_kernel(const float* __restrict__ sb,
                         const float* __restrict__ params,
                         const float* __restrict__ hw,
                         const float* __restrict__ hb,
                         float* __restrict__ out) {
    const int lane = threadIdx.x;
    const int row  = blockIdx.x;

    // ---- per-row element load first: latency overlaps everything below ----
    int idx = row * NW + ((lane < NW) ? lane : (NW - 1));
    float x = sb[idx];

    // ---- full min/max over all 1152 inputs: 9 float4 per lane (MLP=9) ----
    const float4* sb4 = (const float4*)sb;
    float4 v0 = sb4[lane];
    float4 v1 = sb4[lane + 32];
    float4 v2 = sb4[lane + 64];
    float4 v3 = sb4[lane + 96];
    float4 v4 = sb4[lane + 128];
    float4 v5 = sb4[lane + 160];
    float4 v6 = sb4[lane + 192];
    float4 v7 = sb4[lane + 224];
    float4 v8 = sb4[lane + 256];

    // ---- per-wire constants on lanes < NW (overlaps load latency) ----
    float cA = 0.0f, sB = 0.0f, wgt = 0.0f, bias = 0.0f;
    if (lane < NW) {
        float alpha = params[lane * 3 + 0];
        float beta  = params[lane * 3 + 1];
        cA  = __cosf(alpha) * __cosf(beta);
        sB  = __sinf(beta);
        wgt = hw[lane];
    }
    if (lane == 0) bias = hb[0];

    float a0 = fminf(fminf(v0.x, v0.y), fminf(v0.z, v0.w));
    float a1 = fminf(fminf(v1.x, v1.y), fminf(v1.z, v1.w));
    float a2 = fminf(fminf(v2.x, v2.y), fminf(v2.z, v2.w));
    float a3 = fminf(fminf(v3.x, v3.y), fminf(v3.z, v3.w));
    float a4 = fminf(fminf(v4.x, v4.y), fminf(v4.z, v4.w));
    float a5 = fminf(fminf(v5.x, v5.y), fminf(v5.z, v5.w));
    float a6 = fminf(fminf(v6.x, v6.y), fminf(v6.z, v6.w));
    float a7 = fminf(fminf(v7.x, v7.y), fminf(v7.z, v7.w));
    float a8 = fminf(fminf(v8.x, v8.y), fminf(v8.z, v8.w));
    float mn = fminf(fminf(fminf(a0, a1), fminf(a2, a3)),
                     fminf(fminf(a4, a5), fminf(a6, fminf(a7, a8))));
    float b0 = fmaxf(fmaxf(v0.x, v0.y), fmaxf(v0.z, v0.w));
    float b1 = fmaxf(fmaxf(v1.x, v1.y), fmaxf(v1.z, v1.w));
    float b2 = fmaxf(fmaxf(v2.x, v2.y), fmaxf(v2.z, v2.w));
    float b3 = fmaxf(fmaxf(v3.x, v3.y), fmaxf(v3.z, v3.w));
    float b4 = fmaxf(fmaxf(v4.x, v4.y), fmaxf(v4.z, v4.w));
    float b5 = fmaxf(fmaxf(v5.x, v5.y), fmaxf(v5.z, v5.w));
    float b6 = fmaxf(fmaxf(v6.x, v6.y), fmaxf(v6.z, v6.w));
    float b7 = fmaxf(fmaxf(v7.x, v7.y), fmaxf(v7.z, v7.w));
    float b8 = fmaxf(fmaxf(v8.x, v8.y), fmaxf(v8.z, v8.w));
    float mx = fmaxf(fmaxf(fmaxf(b0, b1), fmaxf(b2, b3)),
                     fmaxf(fmaxf(b4, b5), fmaxf(b6, fmaxf(b7, b8))));

    // ---- warp min/max reduce (two independent SHFL chains, dual-issued) ----
#pragma unroll
    for (int s = 16; s > 0; s >>= 1) {
        mn = fminf(mn, __shfl_xor_sync(0xFFFFFFFFu, mn, s));
        mx = fmaxf(mx, __shfl_xor_sync(0xFFFFFFFFu, mx, s));
    }

    // scale via MUFU reciprocal (approximate divide — well within tolerance)
    const float scale = __fdividef(2.0f * CUDART_PI_F, mx - mn);
    float theta = fmaf(x - mn, scale, -CUDART_PI_F);
    float sz, cz;
    __sincosf(theta, &sz, &cz);

    float zl = __shfl_up_sync(0xFFFFFFFFu, cz, 1);    // cz[i-1]
    float zr = __shfl_down_sync(0xFFFFFFFFu, cz, 1);  // cz[i+1]
    if (lane == 0)      zl = 1.0f;
    if (lane == NW - 1) zr = 1.0f;

    float term = wgt * fmaf(cA, cz, -sB * sz * zl * zr) + bias;  // wgt=0 on lanes>=NW

#pragma unroll
    for (int s = 16; s > 0; s >>= 1)
        term += __shfl_xor_sync(0xFFFFFFFFu, term, s);

    if (lane == 0) out[row] = term;
}

extern "C" void kernel_launch(void* const* d_in, const int* in_sizes, int n_in,
                              void* d_out, int out_size) {
    const float* state_batch = (const float*)d_in[0]; // (64, 18)
    const float* params      = (const float*)d_in[1]; // (18, 3)
    const float* head_w      = (const float*)d_in[2]; // (1, 18)
    const float* head_b      = (const float*)d_in[3]; // (1,)
    float* out = (float*)d_out;                       // (64,)

    qcircuit_analytic_kernel<<<NB, 32>>>(state_batch, params, head_w, head_b, out);
}